// round 11
// baseline (speedup 1.0000x reference)
#include <cuda_runtime.h>
#include <cuda_fp16.h>
#include <math.h>

// ---------------- problem constants ----------------
#define CDIM 128
#define NTOT 260000
#define TROWS 720000
#define OUTD 10

static const int kNR[4]  = {40000, 120000, 80000, 20000};
static const int kOFF[4] = {0, 40000, 160000, 240000};

// ---------------- device scratch (static, sanctioned) ----------------
__device__ float  g_x[(size_t)NTOT * CDIM];    // features (in-place across layers)
__device__ float  g_m[(size_t)NTOT * CDIM];    // message accumulators (all ranks)
__device__ __half g_t[(size_t)TROWS * CDIM];   // transformed features, fp16, segmented

// ---------------- small utility kernels ----------------
__global__ void zero_f4(float4* __restrict__ p, int n4) {
    int i = blockIdx.x * blockDim.x + threadIdx.x;
    if (i < n4) p[i] = make_float4(0.f, 0.f, 0.f, 0.f);
}

__global__ void sigmoid_f4(const float4* __restrict__ in, float4* __restrict__ out, int n4) {
    int i = blockIdx.x * blockDim.x + threadIdx.x;
    if (i >= n4) return;
    float4 v = in[i];
    v.x = 1.f / (1.f + expf(-v.x));
    v.y = 1.f / (1.f + expf(-v.y));
    v.z = 1.f / (1.f + expf(-v.z));
    v.w = 1.f / (1.f + expf(-v.w));
    out[i] = v;
}

// ---------------- tf32 GEMM with cp.async double buffering ----------------
// C[M,128] (fp16) = A[M,128] @ B[128,128], 128x128 tile, 8 warps, warp tile 32x64.
// fp32 staged raw via cp.async; cvt.rna.tf32 applied at fragment-load time.

__device__ __forceinline__ unsigned f2tf32(float f) {
    unsigned u;
    asm("cvt.rna.tf32.f32 %0, %1;" : "=r"(u) : "f"(f));
    return u;
}

__device__ __forceinline__ void cp16(float* s, const float* g) {
    unsigned sa = (unsigned)__cvta_generic_to_shared(s);
    asm volatile("cp.async.ca.shared.global [%0], [%1], 16;" :: "r"(sa), "l"(g));
}

__device__ __forceinline__ void mma_tf32(float* c, const unsigned* a, unsigned b0, unsigned b1) {
    asm volatile(
        "mma.sync.aligned.m16n8k8.row.col.f32.tf32.tf32.f32 "
        "{%0,%1,%2,%3}, {%4,%5,%6,%7}, {%8,%9}, {%0,%1,%2,%3};"
        : "+f"(c[0]), "+f"(c[1]), "+f"(c[2]), "+f"(c[3])
        : "r"(a[0]), "r"(a[1]), "r"(a[2]), "r"(a[3]), "r"(b0), "r"(b1));
}

#define ASTRIDE 36    // A smem row stride (floats): 32 + 4
#define BSTRIDE 132   // B smem row stride (floats): 128 + 4
#define ASEG (128 * ASTRIDE)  // 4608
#define BSEG (32 * BSTRIDE)   // 4224
#define GEMM_SMEM ((2 * ASEG + 2 * BSEG) * 4)  // 70656 bytes

__global__ __launch_bounds__(256, 2) void gemm_tf32_ca(const float* __restrict__ A,
                                                       const float* __restrict__ B,
                                                       __half* __restrict__ T, int M) {
    extern __shared__ float sm[];
    float* As = sm;               // [2][128][36]
    float* Bs = sm + 2 * ASEG;    // [2][32][132]

    const int tid  = threadIdx.x;
    const int wid  = tid >> 5;
    const int lane = tid & 31;
    const int g    = lane >> 2;
    const int t4   = lane & 3;
    const int mbase = (wid >> 1) * 32;
    const int nbase = (wid & 1) * 64;
    const int rowBase = blockIdx.x * 128;

    // staging roles
    const int srow  = tid >> 1;          // A row 0..127 (2 thr/row)
    const int skoff = (tid & 1) * 16;    // k offset 0/16
    const int arow  = rowBase + srow;
    const bool aok  = (arow < M);
    const int bk = tid >> 3;             // B k-row 0..31 (8 thr/row)
    const int bn = (tid & 7) * 16;       // n offset

    float acc[2][8][4];
#pragma unroll
    for (int mi = 0; mi < 2; mi++)
#pragma unroll
        for (int ni = 0; ni < 8; ni++)
#pragma unroll
            for (int q = 0; q < 4; q++) acc[mi][ni][q] = 0.f;

    // --- stage chunk c into buffer buf ---
#define STAGE(buf, c)                                                          \
    do {                                                                       \
        const int K0 = (c) * 32;                                               \
        if (aok) {                                                             \
            const float* gs = A + (size_t)arow * 128 + K0 + skoff;             \
            float* ds = As + (buf) * ASEG + srow * ASTRIDE + skoff;            \
            _Pragma("unroll") for (int j = 0; j < 4; j++) cp16(ds + j * 4, gs + j * 4); \
        }                                                                      \
        const float* gb = B + (size_t)(K0 + bk) * 128 + bn;                    \
        float* db = Bs + (buf) * BSEG + bk * BSTRIDE + bn;                     \
        _Pragma("unroll") for (int j = 0; j < 4; j++) cp16(db + j * 4, gb + j * 4); \
        asm volatile("cp.async.commit_group;");                                \
    } while (0)

    STAGE(0, 0);
    int buf = 0;
#pragma unroll
    for (int c = 0; c < 4; c++) {
        if (c < 3) {
            STAGE(buf ^ 1, c + 1);
            asm volatile("cp.async.wait_group 1;");
        } else {
            asm volatile("cp.async.wait_group 0;");
        }
        __syncthreads();

        const float* Ab = As + buf * ASEG;
        const float* Bb = Bs + buf * BSEG;
#pragma unroll
        for (int kt = 0; kt < 4; kt++) {
            const int kk = kt * 8;
            unsigned a[2][4];
#pragma unroll
            for (int mi = 0; mi < 2; mi++) {
                int base = (mbase + mi * 16 + g) * ASTRIDE + kk + t4;
                a[mi][0] = f2tf32(Ab[base]);
                a[mi][1] = f2tf32(Ab[base + 8 * ASTRIDE]);
                a[mi][2] = f2tf32(Ab[base + 4]);
                a[mi][3] = f2tf32(Ab[base + 8 * ASTRIDE + 4]);
            }
#pragma unroll
            for (int ni = 0; ni < 8; ni++) {
                int bb = (kk + t4) * BSTRIDE + nbase + ni * 8 + g;
                unsigned b0 = f2tf32(Bb[bb]);
                unsigned b1 = f2tf32(Bb[bb + 4 * BSTRIDE]);
                mma_tf32(acc[0][ni], a[0], b0, b1);
                mma_tf32(acc[1][ni], a[1], b0, b1);
            }
        }
        __syncthreads();
        buf ^= 1;
    }

    // ---- epilogue: fp16 stores ----
#pragma unroll
    for (int mi = 0; mi < 2; mi++) {
        int r0 = rowBase + mbase + mi * 16 + g;
        int r1 = r0 + 8;
#pragma unroll
        for (int ni = 0; ni < 8; ni++) {
            int col = nbase + ni * 8 + t4 * 2;
            if (r0 < M)
                *(__half2*)(T + (size_t)r0 * 128 + col) =
                    __floats2half2_rn(acc[mi][ni][0], acc[mi][ni][1]);
            if (r1 < M)
                *(__half2*)(T + (size_t)r1 * 128 + col) =
                    __floats2half2_rn(acc[mi][ni][2], acc[mi][ni][3]);
        }
    }
}

// ---------------- batched SpMM (up to 3 COO segments -> one m slice) ----------------
struct SpmmSegs {
    const int*    rows[3];
    const int*    cols[3];
    const float*  vals[3];
    const __half* t[3];
    int cum[4];   // cumulative edge offsets, cum[0]=0
    int nseg;
};

__global__ void spmm_multi(SpmmSegs P, float* __restrict__ m) {
    int gid = blockIdx.x * blockDim.x + threadIdx.x;
    int e = gid >> 5;
    int lane = gid & 31;
    if (e >= P.cum[P.nseg]) return;
    int s = 0;
    if (P.nseg > 1 && e >= P.cum[1]) s = 1;
    if (P.nseg > 2 && e >= P.cum[2]) s = 2;
    int le = e - P.cum[s];
    int r = __ldg(P.rows[s] + le);
    int c = __ldg(P.cols[s] + le);
    float v = __ldg(P.vals[s] + le);
    uint2 hraw = *(const uint2*)(P.t[s] + (size_t)c * 128 + lane * 4);
    __half2 h0 = *(__half2*)&hraw.x;
    __half2 h1 = *(__half2*)&hraw.y;
    float2 f0 = __half22float2(h0);
    float2 f1 = __half22float2(h1);
    float* dst = m + (size_t)r * 128 + lane * 4;
    asm volatile("red.global.add.v4.f32 [%0], {%1,%2,%3,%4};"
                 :: "l"(dst), "f"(f0.x * v), "f"(f0.y * v), "f"(f1.x * v), "f"(f1.y * v)
                 : "memory");
}

// ---------------- head: softmax(x @ W + b) ----------------
__global__ __launch_bounds__(256) void head_kernel(const float* __restrict__ x,
                                                   const float* __restrict__ W,
                                                   const float* __restrict__ b,
                                                   float* __restrict__ out, int M) {
    __shared__ float Ws[128 * OUTD];
    __shared__ float bs[OUTD];
    int tid = threadIdx.x;
    for (int i = tid; i < 128 * OUTD; i += 256) Ws[i] = W[i];
    if (tid < OUTD) bs[tid] = b[tid];
    __syncthreads();
    int lane = tid & 31;
    int row = blockIdx.x * 8 + (tid >> 5);
    if (row >= M) return;
    float xv[4];
#pragma unroll
    for (int q = 0; q < 4; q++) xv[q] = x[(size_t)row * 128 + q * 32 + lane];
    float e[OUTD];
    float mx = -1e30f;
#pragma unroll
    for (int j = 0; j < OUTD; j++) {
        float p = 0.f;
#pragma unroll
        for (int q = 0; q < 4; q++) p = fmaf(xv[q], Ws[(q * 32 + lane) * OUTD + j], p);
#pragma unroll
        for (int s = 16; s; s >>= 1) p += __shfl_xor_sync(0xffffffffu, p, s);
        e[j] = p + bs[j];
        mx = fmaxf(mx, e[j]);
    }
    float sum = 0.f;
#pragma unroll
    for (int j = 0; j < OUTD; j++) { e[j] = expf(e[j] - mx); sum += e[j]; }
    if (lane == 0) {
        float inv = 1.f / sum;
#pragma unroll
        for (int j = 0; j < OUTD; j++) out[(size_t)row * OUTD + j] = e[j] * inv;
    }
}

// ---------------- launch ----------------
extern "C" void kernel_launch(void* const* d_in, const int* in_sizes, int n_in,
                              void* d_out, int out_size) {
    (void)in_sizes; (void)n_in; (void)out_size;

    const int* adj_row[4]; const int* adj_col[4]; const float* adj_val[4];
    for (int r = 0; r < 4; r++) {
        adj_row[r] = (const int*)d_in[4 + 3 * r];
        adj_col[r] = (const int*)d_in[5 + 3 * r];
        adj_val[r] = (const float*)d_in[6 + 3 * r];
    }
    const int* inc_row[3]; const int* inc_col[3]; const float* inc_val[3];
    for (int i = 0; i < 3; i++) {
        inc_row[i] = (const int*)d_in[16 + 3 * i];
        inc_col[i] = (const int*)d_in[17 + 3 * i];
        inc_val[i] = (const float*)d_in[18 + 3 * i];
    }
    const float* W_same = (const float*)d_in[25];  // [2,4,128,128]
    const float* W_h2l  = (const float*)d_in[26];  // [2,3,128,128]
    const float* W_l2h  = (const float*)d_in[27];  // [2,3,128,128]
    const float* W_out  = (const float*)d_in[28];  // [128,10]
    const float* b_out  = (const float*)d_in[29];  // [10]

    static const int kADJ[4] = {320000, 960000, 640000, 160000};
    static const int kINC[3] = {240000, 240000, 80000};

    float *x, *m; __half* t;
    cudaGetSymbolAddress((void**)&x, g_x);
    cudaGetSymbolAddress((void**)&m, g_m);
    cudaGetSymbolAddress((void**)&t, g_t);

    cudaFuncSetAttribute(gemm_tf32_ca, cudaFuncAttributeMaxDynamicSharedMemorySize, GEMM_SMEM);

    const size_t WSZ = (size_t)CDIM * CDIM;

    // t-arena segments (rows): 10 GEMM outputs per layer
    static const int tOff[10]    = {0, 40000, 160000, 280000, 360000, 400000, 480000, 500000, 620000, 640000};
    static const int tSrc[10]    = {0, 1, 1, 2, 0, 2, 3, 1, 3, 2};

    for (int l = 0; l < 2; l++) {
        const float* cur[4];
        for (int rr = 0; rr < 4; rr++)
            cur[rr] = (l == 0) ? (const float*)d_in[rr] : (x + (size_t)kOFF[rr] * CDIM);

        const float* Wseg[10] = {
            W_same + (size_t)(l * 4 + 0) * WSZ,  // s0: r0 same
            W_h2l  + (size_t)(l * 3 + 0) * WSZ,  // s1: r0 h2l (src x1)
            W_same + (size_t)(l * 4 + 1) * WSZ,  // s2: r1 same
            W_h2l  + (size_t)(l * 3 + 1) * WSZ,  // s3: r1 h2l (src x2)
            W_l2h  + (size_t)(l * 3 + 0) * WSZ,  // s4: r1 l2h (src x0)
            W_same + (size_t)(l * 4 + 2) * WSZ,  // s5: r2 same
            W_h2l  + (size_t)(l * 3 + 2) * WSZ,  // s6: r2 h2l (src x3)
            W_l2h  + (size_t)(l * 3 + 1) * WSZ,  // s7: r2 l2h (src x1)
            W_same + (size_t)(l * 4 + 3) * WSZ,  // s8: r3 same
            W_l2h  + (size_t)(l * 3 + 2) * WSZ   // s9: r3 l2h (src x2)
        };

        // phase 1: all 10 GEMMs (read cur x, write fp16 t segments)
        for (int s = 0; s < 10; s++) {
            int M = kNR[tSrc[s]];
            gemm_tf32_ca<<<(M + 127) / 128, 256, GEMM_SMEM>>>(
                cur[tSrc[s]], Wseg[s], t + (size_t)tOff[s] * CDIM, M);
        }

        // phase 2: per target rank: zero -> batched spmm -> sigmoid
        for (int r = 0; r < 4; r++) {
            int n4 = kNR[r] * (CDIM / 4);
            float* mr = m + (size_t)kOFF[r] * CDIM;
            zero_f4<<<(n4 + 255) / 256, 256>>>((float4*)mr, n4);

            SpmmSegs P;
            int ns = 0;
            P.cum[0] = 0;
            // same-rank adjacency
            P.rows[ns] = adj_row[r]; P.cols[ns] = adj_col[r]; P.vals[ns] = adj_val[r];
            P.t[ns] = t + (size_t)tOff[r == 0 ? 0 : (r == 1 ? 2 : (r == 2 ? 5 : 8))] * CDIM;
            P.cum[ns + 1] = P.cum[ns] + kADJ[r]; ns++;
            // high-to-low: inc_{r+1} @ t(h2l)
            if (r < 3) {
                static const int h2lSeg[3] = {1, 3, 6};
                P.rows[ns] = inc_row[r]; P.cols[ns] = inc_col[r]; P.vals[ns] = inc_val[r];
                P.t[ns] = t + (size_t)tOff[h2lSeg[r]] * CDIM;
                P.cum[ns + 1] = P.cum[ns] + kINC[r]; ns++;
            }
            // low-to-high: inc_r^T @ t(l2h)
            if (r > 0) {
                static const int l2hSeg[3] = {4, 7, 9};
                P.rows[ns] = inc_col[r - 1]; P.cols[ns] = inc_row[r - 1]; P.vals[ns] = inc_val[r - 1];
                P.t[ns] = t + (size_t)tOff[l2hSeg[r - 1]] * CDIM;
                P.cum[ns + 1] = P.cum[ns] + kINC[r - 1]; ns++;
            }
            P.nseg = ns;
            int totE = P.cum[ns];
            spmm_multi<<<((size_t)totE * 32 + 255) / 256, 256>>>(P, mr);

            sigmoid_f4<<<(n4 + 255) / 256, 256>>>((const float4*)mr,
                                                  (float4*)(x + (size_t)kOFF[r] * CDIM), n4);
        }
    }

    head_kernel<<<(kNR[0] + 7) / 8, 256>>>(x, W_out, b_out, (float*)d_out, kNR[0]);
}

// round 13
// speedup vs baseline: 2.4327x; 2.4327x over previous
#include <cuda_runtime.h>
#include <cuda_fp16.h>
#include <math.h>

// ---------------- problem constants ----------------
#define CDIM 128
#define NTOT 260000
#define MAXN 120000
#define OUTD 10

static const int kNR[4]  = {40000, 120000, 80000, 20000};
static const int kADJ[4] = {320000, 960000, 640000, 160000};
static const int kINC[3] = {240000, 240000, 80000};
static const int kOFF[4] = {0, 40000, 160000, 240000};

// ---------------- device scratch (static, sanctioned) ----------------
__device__ float  g_xa[(size_t)NTOT * CDIM];   // layer-0 output
__device__ float  g_xb[(size_t)NTOT * CDIM];   // layer-1 output
__device__ __half g_t [(size_t)MAXN * CDIM];   // transformed features (fp16)
__device__ float  g_m [(size_t)MAXN * CDIM];   // message accumulator

// ---------------- small utility kernels ----------------
__global__ void zero_f4(float4* __restrict__ p, int n4) {
    int i = blockIdx.x * blockDim.x + threadIdx.x;
    if (i < n4) p[i] = make_float4(0.f, 0.f, 0.f, 0.f);
}

__global__ void sigmoid_f4(const float4* __restrict__ in, float4* __restrict__ out, int n4) {
    int i = blockIdx.x * blockDim.x + threadIdx.x;
    if (i >= n4) return;
    float4 v = in[i];
    v.x = 1.f / (1.f + expf(-v.x));
    v.y = 1.f / (1.f + expf(-v.y));
    v.z = 1.f / (1.f + expf(-v.z));
    v.w = 1.f / (1.f + expf(-v.w));
    out[i] = v;
}

// ---------------- tf32 tensor-core GEMM: T[M,128](fp16) = A[M,128] @ B[128,128] ----
// Block: 256 threads (8 warps), tile 128x128, warp tile 32x64. K chunked by 32,
// staged in smem with cvt.rna.tf32 at staging time (round-7 proven body).

__device__ __forceinline__ unsigned f2tf32(float f) {
    unsigned u;
    asm("cvt.rna.tf32.f32 %0, %1;" : "=r"(u) : "f"(f));
    return u;
}

__device__ __forceinline__ void mma_tf32(float* c, const unsigned* a, unsigned b0, unsigned b1) {
    asm volatile(
        "mma.sync.aligned.m16n8k8.row.col.f32.tf32.tf32.f32 "
        "{%0,%1,%2,%3}, {%4,%5,%6,%7}, {%8,%9}, {%0,%1,%2,%3};"
        : "+f"(c[0]), "+f"(c[1]), "+f"(c[2]), "+f"(c[3])
        : "r"(a[0]), "r"(a[1]), "r"(a[2]), "r"(a[3]), "r"(b0), "r"(b1));
}

#define SMS 36  // smem row stride (u32): 32 + 4 pad -> conflict-free frag loads

__global__ __launch_bounds__(256, 2) void gemm_tf32(const float* __restrict__ A,
                                                    const float* __restrict__ B,
                                                    __half* __restrict__ T, int M) {
    __shared__ unsigned As[128 * SMS];  // row-major [m][k-chunk]
    __shared__ unsigned Bs[128 * SMS];  // n-major   [n][k-chunk]

    const int tid  = threadIdx.x;
    const int wid  = tid >> 5;
    const int lane = tid & 31;
    const int g    = lane >> 2;    // 0..7
    const int t4   = lane & 3;     // 0..3
    const int mbase = (wid >> 1) * 32;   // warp M offset in tile
    const int nbase = (wid & 1) * 64;    // warp N offset in tile
    const int rowBase = blockIdx.x * 128;

    // staging roles
    const int srow = tid >> 1;           // 0..127  (A row / B col)
    const int skq  = (tid & 1) * 16;     // 0 or 16 (k quarter)
    const int arow = rowBase + srow;
    const bool arow_ok = (arow < M);

    float acc[2][8][4];
#pragma unroll
    for (int mi = 0; mi < 2; mi++)
#pragma unroll
        for (int ni = 0; ni < 8; ni++)
#pragma unroll
            for (int q = 0; q < 4; q++) acc[mi][ni][q] = 0.f;

    for (int c = 0; c < 4; ++c) {
        const int K0 = c * 32;
        // ---- stage A chunk: row srow, k [K0+skq, +16) ----
#pragma unroll
        for (int j = 0; j < 4; j++) {
            float4 v = make_float4(0.f, 0.f, 0.f, 0.f);
            if (arow_ok)
                v = *(const float4*)(A + (size_t)arow * 128 + K0 + skq + j * 4);
            unsigned* dst = &As[srow * SMS + skq + j * 4];
            dst[0] = f2tf32(v.x); dst[1] = f2tf32(v.y);
            dst[2] = f2tf32(v.z); dst[3] = f2tf32(v.w);
        }
        // ---- stage B chunk transposed: col srow, k [K0+skq, +16) ----
#pragma unroll
        for (int j = 0; j < 16; j++) {
            float bv = B[(size_t)(K0 + skq + j) * 128 + srow];
            Bs[srow * SMS + skq + j] = f2tf32(bv);
        }
        __syncthreads();

        // ---- compute 4 k-steps of 8 ----
#pragma unroll
        for (int kt = 0; kt < 4; kt++) {
            const int kk = kt * 8;
            unsigned a[2][4];
#pragma unroll
            for (int mi = 0; mi < 2; mi++) {
                int r0 = (mbase + mi * 16 + g) * SMS + kk + t4;
                a[mi][0] = As[r0];
                a[mi][1] = As[r0 + 8 * SMS];
                a[mi][2] = As[r0 + 4];
                a[mi][3] = As[r0 + 8 * SMS + 4];
            }
#pragma unroll
            for (int ni = 0; ni < 8; ni++) {
                int cb = (nbase + ni * 8 + g) * SMS + kk + t4;
                unsigned b0 = Bs[cb];
                unsigned b1 = Bs[cb + 4];
                mma_tf32(acc[0][ni], a[0], b0, b1);
                mma_tf32(acc[1][ni], a[1], b0, b1);
            }
        }
        __syncthreads();
    }

    // ---- epilogue: fp16 stores ----
#pragma unroll
    for (int mi = 0; mi < 2; mi++) {
        int r0 = rowBase + mbase + mi * 16 + g;
        int r1 = r0 + 8;
#pragma unroll
        for (int ni = 0; ni < 8; ni++) {
            int col = nbase + ni * 8 + t4 * 2;
            if (r0 < M)
                *(__half2*)(T + (size_t)r0 * 128 + col) =
                    __floats2half2_rn(acc[mi][ni][0], acc[mi][ni][1]);
            if (r1 < M)
                *(__half2*)(T + (size_t)r1 * 128 + col) =
                    __floats2half2_rn(acc[mi][ni][2], acc[mi][ni][3]);
        }
    }
}

// ---------------- SpMM: m[row[e]] += val[e] * t[col[e]]  (fp16 gather) ----------------
__global__ void spmm_edge(const int* __restrict__ rows, const int* __restrict__ cols,
                          const float* __restrict__ vals, const __half* __restrict__ t,
                          float* __restrict__ m, int nnz) {
    int gid = blockIdx.x * blockDim.x + threadIdx.x;
    int e = gid >> 5;
    if (e >= nnz) return;
    int lane = gid & 31;
    int r = __ldg(rows + e);
    int c = __ldg(cols + e);
    float v = __ldg(vals + e);
    uint2 hraw = *(const uint2*)(t + (size_t)c * 128 + lane * 4);
    __half2 h0 = *(__half2*)&hraw.x;
    __half2 h1 = *(__half2*)&hraw.y;
    float2 f0 = __half22float2(h0);
    float2 f1 = __half22float2(h1);
    float* dst = m + (size_t)r * 128 + lane * 4;
    asm volatile("red.global.add.v4.f32 [%0], {%1,%2,%3,%4};"
                 :: "l"(dst), "f"(f0.x * v), "f"(f0.y * v), "f"(f1.x * v), "f"(f1.y * v)
                 : "memory");
}

// ---------------- head: softmax(x @ W + b), one warp per row ----------------
__global__ __launch_bounds__(256) void head_kernel(const float* __restrict__ x,
                                                   const float* __restrict__ W,
                                                   const float* __restrict__ b,
                                                   float* __restrict__ out, int M) {
    __shared__ float Ws[128 * OUTD];
    __shared__ float bs[OUTD];
    int tid = threadIdx.x;
    for (int i = tid; i < 128 * OUTD; i += 256) Ws[i] = W[i];
    if (tid < OUTD) bs[tid] = b[tid];
    __syncthreads();
    int lane = tid & 31;
    int row = blockIdx.x * 8 + (tid >> 5);
    if (row >= M) return;
    float xv[4];
#pragma unroll
    for (int q = 0; q < 4; q++) xv[q] = x[(size_t)row * 128 + q * 32 + lane];
    float e[OUTD];
    float mx = -1e30f;
#pragma unroll
    for (int j = 0; j < OUTD; j++) {
        float p = 0.f;
#pragma unroll
        for (int q = 0; q < 4; q++) p = fmaf(xv[q], Ws[(q * 32 + lane) * OUTD + j], p);
#pragma unroll
        for (int s = 16; s; s >>= 1) p += __shfl_xor_sync(0xffffffffu, p, s);
        e[j] = p + bs[j];
        mx = fmaxf(mx, e[j]);
    }
    float sum = 0.f;
#pragma unroll
    for (int j = 0; j < OUTD; j++) { e[j] = expf(e[j] - mx); sum += e[j]; }
    if (lane == 0) {
        float inv = 1.f / sum;
#pragma unroll
        for (int j = 0; j < OUTD; j++) out[(size_t)row * OUTD + j] = e[j] * inv;
    }
}

// ---------------- launch ----------------
extern "C" void kernel_launch(void* const* d_in, const int* in_sizes, int n_in,
                              void* d_out, int out_size) {
    (void)in_sizes; (void)n_in; (void)out_size;

    const int* adj_row[4]; const int* adj_col[4]; const float* adj_val[4];
    for (int r = 0; r < 4; r++) {
        adj_row[r] = (const int*)d_in[4 + 3 * r];
        adj_col[r] = (const int*)d_in[5 + 3 * r];
        adj_val[r] = (const float*)d_in[6 + 3 * r];
    }
    const int* inc_row[3]; const int* inc_col[3]; const float* inc_val[3];
    for (int i = 0; i < 3; i++) {
        inc_row[i] = (const int*)d_in[16 + 3 * i];
        inc_col[i] = (const int*)d_in[17 + 3 * i];
        inc_val[i] = (const float*)d_in[18 + 3 * i];
    }
    const float* W_same = (const float*)d_in[25];  // [2,4,128,128]
    const float* W_h2l  = (const float*)d_in[26];  // [2,3,128,128]
    const float* W_l2h  = (const float*)d_in[27];  // [2,3,128,128]
    const float* W_out  = (const float*)d_in[28];  // [128,10]
    const float* b_out  = (const float*)d_in[29];  // [10]

    float *xa, *xb, *m; __half* t;
    cudaGetSymbolAddress((void**)&xa, g_xa);
    cudaGetSymbolAddress((void**)&xb, g_xb);
    cudaGetSymbolAddress((void**)&t,  g_t);
    cudaGetSymbolAddress((void**)&m,  g_m);

    const size_t WSZ = (size_t)CDIM * CDIM;

    for (int l = 0; l < 2; l++) {
        const float* cur[4];
        float* nxt = (l == 0) ? xa : xb;
        for (int rr = 0; rr < 4; rr++)
            cur[rr] = (l == 0) ? (const float*)d_in[rr] : (xa + (size_t)kOFF[rr] * CDIM);

        for (int r = 0; r < 4; r++) {
            int n4 = kNR[r] * (CDIM / 4);
            zero_f4<<<(n4 + 255) / 256, 256>>>((float4*)m, n4);

            // same-rank adjacency message
            gemm_tf32<<<(kNR[r] + 127) / 128, 256>>>(cur[r], W_same + (size_t)(l * 4 + r) * WSZ, t, kNR[r]);
            spmm_edge<<<((size_t)kADJ[r] * 32 + 255) / 256, 256>>>(adj_row[r], adj_col[r], adj_val[r], t, m, kADJ[r]);

            // high-to-low: inc_{r+1} @ (x_{r+1} W_h2l)
            if (r < 3) {
                gemm_tf32<<<(kNR[r + 1] + 127) / 128, 256>>>(cur[r + 1], W_h2l + (size_t)(l * 3 + r) * WSZ, t, kNR[r + 1]);
                spmm_edge<<<((size_t)kINC[r] * 32 + 255) / 256, 256>>>(inc_row[r], inc_col[r], inc_val[r], t, m, kINC[r]);
            }
            // low-to-high: inc_r^T @ (x_{r-1} W_l2h)
            if (r > 0) {
                gemm_tf32<<<(kNR[r - 1] + 127) / 128, 256>>>(cur[r - 1], W_l2h + (size_t)(l * 3 + r - 1) * WSZ, t, kNR[r - 1]);
                spmm_edge<<<((size_t)kINC[r - 1] * 32 + 255) / 256, 256>>>(inc_col[r - 1], inc_row[r - 1], inc_val[r - 1], t, m, kINC[r - 1]);
            }

            sigmoid_f4<<<(n4 + 255) / 256, 256>>>((const float4*)m, (float4*)(nxt + (size_t)kOFF[r] * CDIM), n4);
        }
    }

    head_kernel<<<(kNR[0] + 7) / 8, 256>>>(xb + (size_t)kOFF[0] * CDIM, W_out, b_out, (float*)d_out, kNR[0]);
}

// round 14
// speedup vs baseline: 3.2288x; 1.3273x over previous
#include <cuda_runtime.h>
#include <cuda_fp16.h>
#include <math.h>

// ---------------- problem constants ----------------
#define CDIM 128
#define NTOT 260000
#define OUTD 10
#define EALL 3200000
#define RALL 720000

static const int kNR[4]  = {40000, 120000, 80000, 20000};
static const int kOFF[4] = {0, 40000, 160000, 240000};

// 10 CSR structures: 0-3 adj[r]; 4-6 h2l (inc{i+1} by row); 7-9 l2h (inc{i+1} by col)
static const int sRows[10] = {40000,120000,80000,20000, 40000,120000,80000, 120000,80000,20000};
static const int sNnz [10] = {320000,960000,640000,160000, 240000,240000,80000, 240000,240000,80000};

// ---------------- device scratch (static, sanctioned) ----------------
__device__ float  g_xa[(size_t)NTOT * CDIM];
__device__ float  g_xb[(size_t)NTOT * CDIM];
__device__ __half g_t [(size_t)240000 * CDIM];     // t arena (max concurrent rows, rank1)
__device__ int    g_rowptr[RALL + 10];
__device__ int    g_cursor[RALL];
__device__ int    g_scol[EALL];
__device__ float  g_sval[EALL];

// ---------------- CSR build ----------------
struct BuildTab {
    const int*   keys[10];
    const int*   pcol[10];
    const float* pval[10];
    int nnzCum[11];
    int rpo[10];
    int cno[10];
    int eo[10];
    int nrows[10];
};

__global__ void zero_int(int* __restrict__ p, int n) {
    int i = blockIdx.x * blockDim.x + threadIdx.x;
    if (i < n) p[i] = 0;
}

__global__ void hist_k(BuildTab T, int* __restrict__ cursor) {
    int i = blockIdx.x * blockDim.x + threadIdx.x;
    if (i >= T.nnzCum[10]) return;
    int s = 0;
    while (i >= T.nnzCum[s + 1]) s++;
    int e = i - T.nnzCum[s];
    int k = __ldg(T.keys[s] + e);
    atomicAdd(cursor + T.cno[s] + k, 1);
}

// one block per structure: exclusive scan counts -> rowptr, cursor = rowptr
__global__ __launch_bounds__(1024) void scan_k(BuildTab T, int* __restrict__ cursor,
                                               int* __restrict__ rowptr) {
    int s = blockIdx.x;
    int n = T.nrows[s];
    int* cnt = cursor + T.cno[s];
    int* rp  = rowptr + T.rpo[s];
    __shared__ int ssum[1024];
    int tid = threadIdx.x;
    int chunk = (n + 1023) >> 10;
    int b0 = tid * chunk;
    int sum = 0;
    for (int k = 0; k < chunk; k++) { int i = b0 + k; if (i < n) sum += cnt[i]; }
    ssum[tid] = sum;
    __syncthreads();
    for (int off = 1; off < 1024; off <<= 1) {
        int v = (tid >= off) ? ssum[tid - off] : 0;
        __syncthreads();
        ssum[tid] += v;
        __syncthreads();
    }
    int run = ssum[tid] - sum;
    for (int k = 0; k < chunk; k++) {
        int i = b0 + k;
        if (i < n) { int c = cnt[i]; rp[i] = run; cnt[i] = run; run += c; }
    }
    if (tid == 1023) rp[n] = ssum[1023];
}

__global__ void scatter_k(BuildTab T, int* __restrict__ cursor,
                          int* __restrict__ scol, float* __restrict__ sval) {
    int i = blockIdx.x * blockDim.x + threadIdx.x;
    if (i >= T.nnzCum[10]) return;
    int s = 0;
    while (i >= T.nnzCum[s + 1]) s++;
    int e = i - T.nnzCum[s];
    int k = __ldg(T.keys[s] + e);
    int pos = atomicAdd(cursor + T.cno[s] + k, 1);
    scol[T.eo[s] + pos] = __ldg(T.pcol[s] + e);
    sval[T.eo[s] + pos] = __ldg(T.pval[s] + e);
}

// ---------------- tf32 tensor-core GEMM: T[M,128](fp16) = A[M,128] @ B[128,128] ----
__device__ __forceinline__ unsigned f2tf32(float f) {
    unsigned u;
    asm("cvt.rna.tf32.f32 %0, %1;" : "=r"(u) : "f"(f));
    return u;
}

__device__ __forceinline__ void mma_tf32(float* c, const unsigned* a, unsigned b0, unsigned b1) {
    asm volatile(
        "mma.sync.aligned.m16n8k8.row.col.f32.tf32.tf32.f32 "
        "{%0,%1,%2,%3}, {%4,%5,%6,%7}, {%8,%9}, {%0,%1,%2,%3};"
        : "+f"(c[0]), "+f"(c[1]), "+f"(c[2]), "+f"(c[3])
        : "r"(a[0]), "r"(a[1]), "r"(a[2]), "r"(a[3]), "r"(b0), "r"(b1));
}

#define SMS 36

__global__ __launch_bounds__(256, 2) void gemm_tf32(const float* __restrict__ A,
                                                    const float* __restrict__ B,
                                                    __half* __restrict__ T, int M) {
    __shared__ unsigned As[128 * SMS];
    __shared__ unsigned Bs[128 * SMS];

    const int tid  = threadIdx.x;
    const int wid  = tid >> 5;
    const int lane = tid & 31;
    const int g    = lane >> 2;
    const int t4   = lane & 3;
    const int mbase = (wid >> 1) * 32;
    const int nbase = (wid & 1) * 64;
    const int rowBase = blockIdx.x * 128;

    const int srow = tid >> 1;
    const int skq  = (tid & 1) * 16;
    const int arow = rowBase + srow;
    const bool arow_ok = (arow < M);

    float acc[2][8][4];
#pragma unroll
    for (int mi = 0; mi < 2; mi++)
#pragma unroll
        for (int ni = 0; ni < 8; ni++)
#pragma unroll
            for (int q = 0; q < 4; q++) acc[mi][ni][q] = 0.f;

    for (int c = 0; c < 4; ++c) {
        const int K0 = c * 32;
#pragma unroll
        for (int j = 0; j < 4; j++) {
            float4 v = make_float4(0.f, 0.f, 0.f, 0.f);
            if (arow_ok)
                v = *(const float4*)(A + (size_t)arow * 128 + K0 + skq + j * 4);
            unsigned* dst = &As[srow * SMS + skq + j * 4];
            dst[0] = f2tf32(v.x); dst[1] = f2tf32(v.y);
            dst[2] = f2tf32(v.z); dst[3] = f2tf32(v.w);
        }
#pragma unroll
        for (int j = 0; j < 16; j++) {
            float bv = B[(size_t)(K0 + skq + j) * 128 + srow];
            Bs[srow * SMS + skq + j] = f2tf32(bv);
        }
        __syncthreads();

#pragma unroll
        for (int kt = 0; kt < 4; kt++) {
            const int kk = kt * 8;
            unsigned a[2][4];
#pragma unroll
            for (int mi = 0; mi < 2; mi++) {
                int r0 = (mbase + mi * 16 + g) * SMS + kk + t4;
                a[mi][0] = As[r0];
                a[mi][1] = As[r0 + 8 * SMS];
                a[mi][2] = As[r0 + 4];
                a[mi][3] = As[r0 + 8 * SMS + 4];
            }
#pragma unroll
            for (int ni = 0; ni < 8; ni++) {
                int cb = (nbase + ni * 8 + g) * SMS + kk + t4;
                unsigned b0 = Bs[cb];
                unsigned b1 = Bs[cb + 4];
                mma_tf32(acc[0][ni], a[0], b0, b1);
                mma_tf32(acc[1][ni], a[1], b0, b1);
            }
        }
        __syncthreads();
    }

#pragma unroll
    for (int mi = 0; mi < 2; mi++) {
        int r0 = rowBase + mbase + mi * 16 + g;
        int r1 = r0 + 8;
#pragma unroll
        for (int ni = 0; ni < 8; ni++) {
            int col = nbase + ni * 8 + t4 * 2;
            if (r0 < M)
                *(__half2*)(T + (size_t)r0 * 128 + col) =
                    __floats2half2_rn(acc[mi][ni][0], acc[mi][ni][1]);
            if (r1 < M)
                *(__half2*)(T + (size_t)r1 * 128 + col) =
                    __floats2half2_rn(acc[mi][ni][2], acc[mi][ni][3]);
        }
    }
}

// ---------------- fused CSR gather SpMM + sigmoid (warp per row) ----------------
struct FSegs {
    const int*    rp[3];
    const int*    col[3];
    const float*  val[3];
    const __half* t[3];
    int nseg;
};

__global__ __launch_bounds__(256) void spmm_sig(FSegs P, float* __restrict__ xout, int nrows) {
    int wid  = threadIdx.x >> 5;
    int lane = threadIdx.x & 31;
    int row  = blockIdx.x * 8 + wid;
    if (row >= nrows) return;

    float ax = 0.f, ay = 0.f, az = 0.f, aw = 0.f;
#pragma unroll
    for (int s = 0; s < 3; s++) {
        if (s < P.nseg) {
            const int* rp = P.rp[s];
            const int* cl = P.col[s];
            const float* vl = P.val[s];
            const __half* tb = P.t[s];
            int b = __ldg(rp + row);
            int e = __ldg(rp + row + 1);
            int j = b;
            for (; j + 1 < e; j += 2) {
                int c0 = __ldg(cl + j), c1 = __ldg(cl + j + 1);
                float v0 = __ldg(vl + j), v1 = __ldg(vl + j + 1);
                uint2 h0 = *(const uint2*)(tb + (size_t)c0 * 128 + lane * 4);
                uint2 h1 = *(const uint2*)(tb + (size_t)c1 * 128 + lane * 4);
                float2 p0 = __half22float2(*(__half2*)&h0.x);
                float2 p1 = __half22float2(*(__half2*)&h0.y);
                float2 q0 = __half22float2(*(__half2*)&h1.x);
                float2 q1 = __half22float2(*(__half2*)&h1.y);
                ax = fmaf(v0, p0.x, ax); ay = fmaf(v0, p0.y, ay);
                az = fmaf(v0, p1.x, az); aw = fmaf(v0, p1.y, aw);
                ax = fmaf(v1, q0.x, ax); ay = fmaf(v1, q0.y, ay);
                az = fmaf(v1, q1.x, az); aw = fmaf(v1, q1.y, aw);
            }
            if (j < e) {
                int c0 = __ldg(cl + j);
                float v0 = __ldg(vl + j);
                uint2 h0 = *(const uint2*)(tb + (size_t)c0 * 128 + lane * 4);
                float2 p0 = __half22float2(*(__half2*)&h0.x);
                float2 p1 = __half22float2(*(__half2*)&h0.y);
                ax = fmaf(v0, p0.x, ax); ay = fmaf(v0, p0.y, ay);
                az = fmaf(v0, p1.x, az); aw = fmaf(v0, p1.y, aw);
            }
        }
    }
    float4 o;
    o.x = 1.f / (1.f + expf(-ax));
    o.y = 1.f / (1.f + expf(-ay));
    o.z = 1.f / (1.f + expf(-az));
    o.w = 1.f / (1.f + expf(-aw));
    *(float4*)(xout + (size_t)row * 128 + lane * 4) = o;
}

// ---------------- head: softmax(x @ W + b), one warp per row ----------------
__global__ __launch_bounds__(256) void head_kernel(const float* __restrict__ x,
                                                   const float* __restrict__ W,
                                                   const float* __restrict__ b,
                                                   float* __restrict__ out, int M) {
    __shared__ float Ws[128 * OUTD];
    __shared__ float bs[OUTD];
    int tid = threadIdx.x;
    for (int i = tid; i < 128 * OUTD; i += 256) Ws[i] = W[i];
    if (tid < OUTD) bs[tid] = b[tid];
    __syncthreads();
    int lane = tid & 31;
    int row = blockIdx.x * 8 + (tid >> 5);
    if (row >= M) return;
    float xv[4];
#pragma unroll
    for (int q = 0; q < 4; q++) xv[q] = x[(size_t)row * 128 + q * 32 + lane];
    float e[OUTD];
    float mx = -1e30f;
#pragma unroll
    for (int j = 0; j < OUTD; j++) {
        float p = 0.f;
#pragma unroll
        for (int q = 0; q < 4; q++) p = fmaf(xv[q], Ws[(q * 32 + lane) * OUTD + j], p);
#pragma unroll
        for (int s = 16; s; s >>= 1) p += __shfl_xor_sync(0xffffffffu, p, s);
        e[j] = p + bs[j];
        mx = fmaxf(mx, e[j]);
    }
    float sum = 0.f;
#pragma unroll
    for (int j = 0; j < OUTD; j++) { e[j] = expf(e[j] - mx); sum += e[j]; }
    if (lane == 0) {
        float inv = 1.f / sum;
#pragma unroll
        for (int j = 0; j < OUTD; j++) out[(size_t)row * OUTD + j] = e[j] * inv;
    }
}

// ---------------- launch ----------------
extern "C" void kernel_launch(void* const* d_in, const int* in_sizes, int n_in,
                              void* d_out, int out_size) {
    (void)in_sizes; (void)n_in; (void)out_size;

    const int* adj_row[4]; const int* adj_col[4]; const float* adj_val[4];
    for (int r = 0; r < 4; r++) {
        adj_row[r] = (const int*)d_in[4 + 3 * r];
        adj_col[r] = (const int*)d_in[5 + 3 * r];
        adj_val[r] = (const float*)d_in[6 + 3 * r];
    }
    const int* inc_row[3]; const int* inc_col[3]; const float* inc_val[3];
    for (int i = 0; i < 3; i++) {
        inc_row[i] = (const int*)d_in[16 + 3 * i];
        inc_col[i] = (const int*)d_in[17 + 3 * i];
        inc_val[i] = (const float*)d_in[18 + 3 * i];
    }
    const float* W_same = (const float*)d_in[25];
    const float* W_h2l  = (const float*)d_in[26];
    const float* W_l2h  = (const float*)d_in[27];
    const float* W_out  = (const float*)d_in[28];
    const float* b_out  = (const float*)d_in[29];

    float *xa, *xb; __half* t;
    int *rowptr, *cursor, *scol; float* sval;
    cudaGetSymbolAddress((void**)&xa, g_xa);
    cudaGetSymbolAddress((void**)&xb, g_xb);
    cudaGetSymbolAddress((void**)&t,  g_t);
    cudaGetSymbolAddress((void**)&rowptr, g_rowptr);
    cudaGetSymbolAddress((void**)&cursor, g_cursor);
    cudaGetSymbolAddress((void**)&scol, g_scol);
    cudaGetSymbolAddress((void**)&sval, g_sval);

    // ---- build tables ----
    BuildTab T;
    T.keys[0] = adj_row[0]; T.keys[1] = adj_row[1]; T.keys[2] = adj_row[2]; T.keys[3] = adj_row[3];
    T.keys[4] = inc_row[0]; T.keys[5] = inc_row[1]; T.keys[6] = inc_row[2];
    T.keys[7] = inc_col[0]; T.keys[8] = inc_col[1]; T.keys[9] = inc_col[2];
    T.pcol[0] = adj_col[0]; T.pcol[1] = adj_col[1]; T.pcol[2] = adj_col[2]; T.pcol[3] = adj_col[3];
    T.pcol[4] = inc_col[0]; T.pcol[5] = inc_col[1]; T.pcol[6] = inc_col[2];
    T.pcol[7] = inc_row[0]; T.pcol[8] = inc_row[1]; T.pcol[9] = inc_row[2];
    T.pval[0] = adj_val[0]; T.pval[1] = adj_val[1]; T.pval[2] = adj_val[2]; T.pval[3] = adj_val[3];
    T.pval[4] = inc_val[0]; T.pval[5] = inc_val[1]; T.pval[6] = inc_val[2];
    T.pval[7] = inc_val[0]; T.pval[8] = inc_val[1]; T.pval[9] = inc_val[2];
    {
        int ec = 0, rc = 0, cc = 0;
        for (int s = 0; s < 10; s++) {
            T.nnzCum[s] = ec; T.eo[s] = ec; T.rpo[s] = rc; T.cno[s] = cc; T.nrows[s] = sRows[s];
            ec += sNnz[s]; rc += sRows[s] + 1; cc += sRows[s];
        }
        T.nnzCum[10] = ec;
    }

    // ---- CSR build (index-only, shared by both layers) ----
    zero_int<<<(RALL + 255) / 256, 256>>>(cursor, RALL);
    hist_k<<<(EALL + 255) / 256, 256>>>(T, cursor);
    scan_k<<<10, 1024>>>(T, cursor, rowptr);
    scatter_k<<<(EALL + 255) / 256, 256>>>(T, cursor, scol, sval);

    // per-rank segment schedule: structure ids + t source ranks
    static const int segStruct[4][3] = {{0, 4, -1}, {1, 5, 7}, {2, 6, 8}, {3, 9, -1}};
    static const int segSrc[4][3]    = {{0, 1, -1}, {1, 2, 0}, {2, 3, 1}, {3, 2, -1}};
    static const int segCnt[4]       = {2, 3, 3, 2};

    const size_t WSZ = (size_t)CDIM * CDIM;

    for (int l = 0; l < 2; l++) {
        const float* cur[4];
        float* nxt = (l == 0) ? xa : xb;
        for (int rr = 0; rr < 4; rr++)
            cur[rr] = (l == 0) ? (const float*)d_in[rr] : (xa + (size_t)kOFF[rr] * CDIM);

        for (int r = 0; r < 4; r++) {
            // weights for each segment of this rank
            const float* Wseg[3];
            Wseg[0] = W_same + (size_t)(l * 4 + r) * WSZ;
            if (r == 0)      { Wseg[1] = W_h2l + (size_t)(l * 3 + 0) * WSZ; }
            else if (r == 1) { Wseg[1] = W_h2l + (size_t)(l * 3 + 1) * WSZ;
                               Wseg[2] = W_l2h + (size_t)(l * 3 + 0) * WSZ; }
            else if (r == 2) { Wseg[1] = W_h2l + (size_t)(l * 3 + 2) * WSZ;
                               Wseg[2] = W_l2h + (size_t)(l * 3 + 1) * WSZ; }
            else             { Wseg[1] = W_l2h + (size_t)(l * 3 + 2) * WSZ; }

            FSegs P;
            P.nseg = segCnt[r];
            size_t toff = 0;
            for (int s = 0; s < segCnt[r]; s++) {
                int src = segSrc[r][s];
                int st  = segStruct[r][s];
                __half* tseg = t + toff * CDIM;
                gemm_tf32<<<(kNR[src] + 127) / 128, 256>>>(cur[src], Wseg[s], tseg, kNR[src]);
                P.rp[s]  = rowptr + [&]{ int rc = 0; for (int q = 0; q < st; q++) rc += sRows[q] + 1; return rc; }();
                P.col[s] = scol + T.eo[st];
                P.val[s] = sval + T.eo[st];
                P.t[s]   = tseg;
                toff += kNR[src];
            }
            spmm_sig<<<(kNR[r] + 7) / 8, 256>>>(P, nxt + (size_t)kOFF[r] * CDIM, kNR[r]);
        }
    }

    head_kernel<<<(kNR[0] + 7) / 8, 256>>>(xb + (size_t)kOFF[0] * CDIM, W_out, b_out, (float*)d_out, kNR[0]);
}

// round 15
// speedup vs baseline: 3.6615x; 1.1340x over previous
#include <cuda_runtime.h>
#include <cuda_fp16.h>
#include <math.h>

// ---------------- problem constants ----------------
#define CDIM 128
#define NTOT 260000
#define OUTD 10
#define EALL 3200000
#define RALL 260000   // merged rows across 4 target ranks
#define TARENA 720000 // t arena rows (all (rank,seg) segments)

static const int kNR[4]  = {40000, 120000, 80000, 20000};
static const int kOFF[4] = {0, 40000, 160000, 240000};
static const int eOff[4] = {0, 560000, 2000000, 2960000};    // merged edges per rank
static const int rpOff[4] = {0, 40001, 160002, 240003};      // rowptr bases (n+1 each)

// ---------------- device scratch (static, sanctioned) ----------------
__device__ float  g_xa[(size_t)NTOT * CDIM];
__device__ float  g_xb[(size_t)NTOT * CDIM];
__device__ __half g_t [(size_t)TARENA * CDIM];
__device__ int    g_rowptr[RALL + 4];
__device__ int    g_cursor[RALL];
__device__ int    g_scol[EALL];
__device__ float  g_sval[EALL];

// ---------------- CSR build (merged per target rank) ----------------
struct BuildTab {
    const int*   keys[10];   // output-row key per edge
    const int*   pcol[10];   // source index per edge
    const float* pval[10];
    int nnzCum[11];
    int cno[10];             // cursor base   = kOFF[target]
    int eo[10];              // edge base     = eOff[target]
    int toff[10];            // t-arena row offset baked into col
};

__global__ void zero_int(int* __restrict__ p, int n) {
    int i = blockIdx.x * blockDim.x + threadIdx.x;
    if (i < n) p[i] = 0;
}

__global__ void hist_k(BuildTab T, int* __restrict__ cursor) {
    int i = blockIdx.x * blockDim.x + threadIdx.x;
    if (i >= T.nnzCum[10]) return;
    int s = 0;
    while (i >= T.nnzCum[s + 1]) s++;
    int e = i - T.nnzCum[s];
    int k = __ldg(T.keys[s] + e);
    atomicAdd(cursor + T.cno[s] + k, 1);
}

struct ScanTab { int n[4]; int cno[4]; int rpo[4]; };

// one block per rank: exclusive scan counts -> rowptr, cursor = row start
__global__ __launch_bounds__(1024) void scan_k(ScanTab S, int* __restrict__ cursor,
                                               int* __restrict__ rowptr) {
    int s = blockIdx.x;
    int n = S.n[s];
    int* cnt = cursor + S.cno[s];
    int* rp  = rowptr + S.rpo[s];
    __shared__ int ssum[1024];
    int tid = threadIdx.x;
    int chunk = (n + 1023) >> 10;
    int b0 = tid * chunk;
    int sum = 0;
    for (int k = 0; k < chunk; k++) { int i = b0 + k; if (i < n) sum += cnt[i]; }
    ssum[tid] = sum;
    __syncthreads();
    for (int off = 1; off < 1024; off <<= 1) {
        int v = (tid >= off) ? ssum[tid - off] : 0;
        __syncthreads();
        ssum[tid] += v;
        __syncthreads();
    }
    int run = ssum[tid] - sum;
    for (int k = 0; k < chunk; k++) {
        int i = b0 + k;
        if (i < n) { int c = cnt[i]; rp[i] = run; cnt[i] = run; run += c; }
    }
    if (tid == 1023) rp[n] = ssum[1023];
}

__global__ void scatter_k(BuildTab T, int* __restrict__ cursor,
                          int* __restrict__ scol, float* __restrict__ sval) {
    int i = blockIdx.x * blockDim.x + threadIdx.x;
    if (i >= T.nnzCum[10]) return;
    int s = 0;
    while (i >= T.nnzCum[s + 1]) s++;
    int e = i - T.nnzCum[s];
    int k = __ldg(T.keys[s] + e);
    int pos = atomicAdd(cursor + T.cno[s] + k, 1);
    scol[T.eo[s] + pos] = T.toff[s] + __ldg(T.pcol[s] + e);
    sval[T.eo[s] + pos] = __ldg(T.pval[s] + e);
}

// ---------------- fp16 tensor-core GEMM: T[M,128](fp16) = A[M,128] @ B[128,128] ----
// 256 threads / 8 warps, tile 128x128, warp tile 32x64, full-K single staging.
// fp16 mantissa == tf32 mantissa (10 bits): accuracy identical to prior tf32 path.

__device__ __forceinline__ void mma_f16(float* c, const unsigned* a, unsigned b0, unsigned b1) {
    asm volatile(
        "mma.sync.aligned.m16n8k16.row.col.f32.f16.f16.f32 "
        "{%0,%1,%2,%3}, {%4,%5,%6,%7}, {%8,%9}, {%0,%1,%2,%3};"
        : "+f"(c[0]), "+f"(c[1]), "+f"(c[2]), "+f"(c[3])
        : "r"(a[0]), "r"(a[1]), "r"(a[2]), "r"(a[3]), "r"(b0), "r"(b1));
}

#define KS 136  // smem row stride in halves: 128 + 8 pad -> conflict-free frags
#define GEMM_SMEM (2 * 128 * KS * 2)  // 69632 bytes

__global__ __launch_bounds__(256, 2) void gemm_f16(const float* __restrict__ A,
                                                   const float* __restrict__ B,
                                                   __half* __restrict__ T, int M) {
    extern __shared__ __half sh[];
    __half* As = sh;               // [128][KS]  row-major (m,k)
    __half* Bs = sh + 128 * KS;    // [128][KS]  n-major   (n,k)

    const int tid  = threadIdx.x;
    const int wid  = tid >> 5;
    const int lane = tid & 31;
    const int g    = lane >> 2;
    const int t4   = lane & 3;
    const int mbase = (wid >> 1) * 32;
    const int nbase = (wid & 1) * 64;
    const int rowBase = blockIdx.x * 128;

    const int srow  = tid >> 1;          // 0..127
    const int shalf = (tid & 1) * 64;    // k-offset (halves)
    const int arow  = rowBase + srow;

    // ---- stage A (full K) ----
    if (arow < M) {
        const float* ga = A + (size_t)arow * 128 + shalf;
        __half* da = As + srow * KS + shalf;
#pragma unroll
        for (int j = 0; j < 16; j++) {
            float4 v = *(const float4*)(ga + j * 4);
            *(__half2*)(da + j * 4)     = __floats2half2_rn(v.x, v.y);
            *(__half2*)(da + j * 4 + 2) = __floats2half2_rn(v.z, v.w);
        }
    } else {
        __half* da = As + srow * KS + shalf;
        __half2 z = __floats2half2_rn(0.f, 0.f);
#pragma unroll
        for (int j = 0; j < 32; j++) *(__half2*)(da + j * 2) = z;
    }
    // ---- stage B transposed: Bs[n][k] = B[k][n] ----
    {
        __half* db = Bs + srow * KS + shalf;
#pragma unroll 16
        for (int j = 0; j < 64; j++)
            db[j] = __float2half_rn(B[(size_t)(shalf + j) * 128 + srow]);
    }
    __syncthreads();

    float acc[2][8][4];
#pragma unroll
    for (int mi = 0; mi < 2; mi++)
#pragma unroll
        for (int ni = 0; ni < 8; ni++)
#pragma unroll
            for (int q = 0; q < 4; q++) acc[mi][ni][q] = 0.f;

#pragma unroll
    for (int kt = 0; kt < 8; kt++) {
        const int k0 = kt * 16;
        unsigned a[2][4];
#pragma unroll
        for (int mi = 0; mi < 2; mi++) {
            int ab = (mbase + mi * 16 + g) * KS + k0 + 2 * t4;
            a[mi][0] = *(const unsigned*)&As[ab];
            a[mi][1] = *(const unsigned*)&As[ab + 8 * KS];
            a[mi][2] = *(const unsigned*)&As[ab + 8];
            a[mi][3] = *(const unsigned*)&As[ab + 8 * KS + 8];
        }
#pragma unroll
        for (int ni = 0; ni < 8; ni++) {
            int bb = (nbase + ni * 8 + g) * KS + k0 + 2 * t4;
            unsigned b0 = *(const unsigned*)&Bs[bb];
            unsigned b1 = *(const unsigned*)&Bs[bb + 8];
            mma_f16(acc[0][ni], a[0], b0, b1);
            mma_f16(acc[1][ni], a[1], b0, b1);
        }
    }

    // ---- epilogue: fp16 stores ----
#pragma unroll
    for (int mi = 0; mi < 2; mi++) {
        int r0 = rowBase + mbase + mi * 16 + g;
        int r1 = r0 + 8;
#pragma unroll
        for (int ni = 0; ni < 8; ni++) {
            int col = nbase + ni * 8 + t4 * 2;
            if (r0 < M)
                *(__half2*)(T + (size_t)r0 * 128 + col) =
                    __floats2half2_rn(acc[mi][ni][0], acc[mi][ni][1]);
            if (r1 < M)
                *(__half2*)(T + (size_t)r1 * 128 + col) =
                    __floats2half2_rn(acc[mi][ni][2], acc[mi][ni][3]);
        }
    }
}

// ---------------- fused merged-CSR gather SpMM + sigmoid (warp per row, MLP4) ----
__global__ __launch_bounds__(256) void spmm_sig(const int* __restrict__ rp,
                                                const int* __restrict__ cl,
                                                const float* __restrict__ vl,
                                                const __half* __restrict__ tb,
                                                float* __restrict__ xout, int nrows) {
    int wid  = threadIdx.x >> 5;
    int lane = threadIdx.x & 31;
    int row  = blockIdx.x * 8 + wid;
    if (row >= nrows) return;

    int b = __ldg(rp + row);
    int e = __ldg(rp + row + 1);
    float ax = 0.f, ay = 0.f, az = 0.f, aw = 0.f;
    int j = b;
    for (; j + 3 < e; j += 4) {
        int c0 = __ldg(cl + j), c1 = __ldg(cl + j + 1);
        int c2 = __ldg(cl + j + 2), c3 = __ldg(cl + j + 3);
        float v0 = __ldg(vl + j), v1 = __ldg(vl + j + 1);
        float v2 = __ldg(vl + j + 2), v3 = __ldg(vl + j + 3);
        uint2 h0 = *(const uint2*)(tb + (size_t)c0 * 128 + lane * 4);
        uint2 h1 = *(const uint2*)(tb + (size_t)c1 * 128 + lane * 4);
        uint2 h2 = *(const uint2*)(tb + (size_t)c2 * 128 + lane * 4);
        uint2 h3 = *(const uint2*)(tb + (size_t)c3 * 128 + lane * 4);
        float2 p0 = __half22float2(*(__half2*)&h0.x), p1 = __half22float2(*(__half2*)&h0.y);
        float2 q0 = __half22float2(*(__half2*)&h1.x), q1 = __half22float2(*(__half2*)&h1.y);
        float2 r0 = __half22float2(*(__half2*)&h2.x), r1 = __half22float2(*(__half2*)&h2.y);
        float2 s0 = __half22float2(*(__half2*)&h3.x), s1 = __half22float2(*(__half2*)&h3.y);
        ax = fmaf(v0, p0.x, ax); ay = fmaf(v0, p0.y, ay); az = fmaf(v0, p1.x, az); aw = fmaf(v0, p1.y, aw);
        ax = fmaf(v1, q0.x, ax); ay = fmaf(v1, q0.y, ay); az = fmaf(v1, q1.x, az); aw = fmaf(v1, q1.y, aw);
        ax = fmaf(v2, r0.x, ax); ay = fmaf(v2, r0.y, ay); az = fmaf(v2, r1.x, az); aw = fmaf(v2, r1.y, aw);
        ax = fmaf(v3, s0.x, ax); ay = fmaf(v3, s0.y, ay); az = fmaf(v3, s1.x, az); aw = fmaf(v3, s1.y, aw);
    }
    for (; j < e; j++) {
        int c0 = __ldg(cl + j);
        float v0 = __ldg(vl + j);
        uint2 h0 = *(const uint2*)(tb + (size_t)c0 * 128 + lane * 4);
        float2 p0 = __half22float2(*(__half2*)&h0.x), p1 = __half22float2(*(__half2*)&h0.y);
        ax = fmaf(v0, p0.x, ax); ay = fmaf(v0, p0.y, ay);
        az = fmaf(v0, p1.x, az); aw = fmaf(v0, p1.y, aw);
    }
    float4 o;
    o.x = 1.f / (1.f + expf(-ax));
    o.y = 1.f / (1.f + expf(-ay));
    o.z = 1.f / (1.f + expf(-az));
    o.w = 1.f / (1.f + expf(-aw));
    *(float4*)(xout + (size_t)row * 128 + lane * 4) = o;
}

// ---------------- head: softmax(x @ W + b), one warp per row ----------------
__global__ __launch_bounds__(256) void head_kernel(const float* __restrict__ x,
                                                   const float* __restrict__ W,
                                                   const float* __restrict__ b,
                                                   float* __restrict__ out, int M) {
    __shared__ float Ws[128 * OUTD];
    __shared__ float bs[OUTD];
    int tid = threadIdx.x;
    for (int i = tid; i < 128 * OUTD; i += 256) Ws[i] = W[i];
    if (tid < OUTD) bs[tid] = b[tid];
    __syncthreads();
    int lane = tid & 31;
    int row = blockIdx.x * 8 + (tid >> 5);
    if (row >= M) return;
    float xv[4];
#pragma unroll
    for (int q = 0; q < 4; q++) xv[q] = x[(size_t)row * 128 + q * 32 + lane];
    float e[OUTD];
    float mx = -1e30f;
#pragma unroll
    for (int j = 0; j < OUTD; j++) {
        float p = 0.f;
#pragma unroll
        for (int q = 0; q < 4; q++) p = fmaf(xv[q], Ws[(q * 32 + lane) * OUTD + j], p);
#pragma unroll
        for (int s = 16; s; s >>= 1) p += __shfl_xor_sync(0xffffffffu, p, s);
        e[j] = p + bs[j];
        mx = fmaxf(mx, e[j]);
    }
    float sum = 0.f;
#pragma unroll
    for (int j = 0; j < OUTD; j++) { e[j] = expf(e[j] - mx); sum += e[j]; }
    if (lane == 0) {
        float inv = 1.f / sum;
#pragma unroll
        for (int j = 0; j < OUTD; j++) out[(size_t)row * OUTD + j] = e[j] * inv;
    }
}

// ---------------- launch ----------------
extern "C" void kernel_launch(void* const* d_in, const int* in_sizes, int n_in,
                              void* d_out, int out_size) {
    (void)in_sizes; (void)n_in; (void)out_size;

    const int* adj_row[4]; const int* adj_col[4]; const float* adj_val[4];
    for (int r = 0; r < 4; r++) {
        adj_row[r] = (const int*)d_in[4 + 3 * r];
        adj_col[r] = (const int*)d_in[5 + 3 * r];
        adj_val[r] = (const float*)d_in[6 + 3 * r];
    }
    const int* inc_row[3]; const int* inc_col[3]; const float* inc_val[3];
    for (int i = 0; i < 3; i++) {
        inc_row[i] = (const int*)d_in[16 + 3 * i];
        inc_col[i] = (const int*)d_in[17 + 3 * i];
        inc_val[i] = (const float*)d_in[18 + 3 * i];
    }
    const float* W_same = (const float*)d_in[25];
    const float* W_h2l  = (const float*)d_in[26];
    const float* W_l2h  = (const float*)d_in[27];
    const float* W_out  = (const float*)d_in[28];
    const float* b_out  = (const float*)d_in[29];

    float *xa, *xb; __half* t;
    int *rowptr, *cursor, *scol; float* sval;
    cudaGetSymbolAddress((void**)&xa, g_xa);
    cudaGetSymbolAddress((void**)&xb, g_xb);
    cudaGetSymbolAddress((void**)&t,  g_t);
    cudaGetSymbolAddress((void**)&rowptr, g_rowptr);
    cudaGetSymbolAddress((void**)&cursor, g_cursor);
    cudaGetSymbolAddress((void**)&scol, g_scol);
    cudaGetSymbolAddress((void**)&sval, g_sval);

    cudaFuncSetAttribute(gemm_f16, cudaFuncAttributeMaxDynamicSharedMemorySize, GEMM_SMEM);

    // structures 0..9: 0-3 adj (target r); 4-6 h2l (target 0..2); 7-9 l2h (target 1..3)
    static const int sNnz[10]  = {320000,960000,640000,160000, 240000,240000,80000, 240000,240000,80000};
    static const int sTgt[10]  = {0,1,2,3, 0,1,2, 1,2,3};
    static const int sToff[10] = {0,160000,400000,620000, 40000,280000,480000, 360000,500000,640000};

    BuildTab T;
    for (int s = 0; s < 4; s++) { T.keys[s] = adj_row[s]; T.pcol[s] = adj_col[s]; T.pval[s] = adj_val[s]; }
    for (int i = 0; i < 3; i++) {
        T.keys[4 + i] = inc_row[i]; T.pcol[4 + i] = inc_col[i]; T.pval[4 + i] = inc_val[i];  // h2l
        T.keys[7 + i] = inc_col[i]; T.pcol[7 + i] = inc_row[i]; T.pval[7 + i] = inc_val[i];  // l2h
    }
    {
        int ec = 0;
        for (int s = 0; s < 10; s++) {
            T.nnzCum[s] = ec; ec += sNnz[s];
            T.cno[s] = kOFF[sTgt[s]];
            T.eo[s]  = eOff[sTgt[s]];
            T.toff[s] = sToff[s];
        }
        T.nnzCum[10] = ec;
    }
    ScanTab S;
    for (int r = 0; r < 4; r++) { S.n[r] = kNR[r]; S.cno[r] = kOFF[r]; S.rpo[r] = rpOff[r]; }

    // ---- CSR build (index-only, shared by both layers) ----
    zero_int<<<(RALL + 255) / 256, 256>>>(cursor, RALL);
    hist_k<<<(EALL + 255) / 256, 256>>>(T, cursor);
    scan_k<<<4, 1024>>>(S, cursor, rowptr);
    scatter_k<<<(EALL + 255) / 256, 256>>>(T, cursor, scol, sval);

    // per-rank GEMM schedule: (src rank, global t-offset, weight kind)
    static const int segCnt[4]    = {2, 3, 3, 2};
    static const int segSrc[4][3] = {{0, 1, -1}, {1, 2, 0}, {2, 3, 1}, {3, 2, -1}};
    static const int segTof[4][3] = {{0, 40000, -1}, {160000, 280000, 360000},
                                     {400000, 480000, 500000}, {620000, 640000, -1}};

    const size_t WSZ = (size_t)CDIM * CDIM;

    for (int l = 0; l < 2; l++) {
        const float* cur[4];
        float* nxt = (l == 0) ? xa : xb;
        for (int rr = 0; rr < 4; rr++)
            cur[rr] = (l == 0) ? (const float*)d_in[rr] : (xa + (size_t)kOFF[rr] * CDIM);

        for (int r = 0; r < 4; r++) {
            const float* Wseg[3];
            Wseg[0] = W_same + (size_t)(l * 4 + r) * WSZ;
            if (r == 0)      { Wseg[1] = W_h2l + (size_t)(l * 3 + 0) * WSZ; }
            else if (r == 1) { Wseg[1] = W_h2l + (size_t)(l * 3 + 1) * WSZ;
                               Wseg[2] = W_l2h + (size_t)(l * 3 + 0) * WSZ; }
            else if (r == 2) { Wseg[1] = W_h2l + (size_t)(l * 3 + 2) * WSZ;
                               Wseg[2] = W_l2h + (size_t)(l * 3 + 1) * WSZ; }
            else             { Wseg[1] = W_l2h + (size_t)(l * 3 + 2) * WSZ; }

            for (int s = 0; s < segCnt[r]; s++) {
                int src = segSrc[r][s];
                gemm_f16<<<(kNR[src] + 127) / 128, 256, GEMM_SMEM>>>(
                    cur[src], Wseg[s], t + (size_t)segTof[r][s] * CDIM, kNR[src]);
            }
            spmm_sig<<<(kNR[r] + 7) / 8, 256>>>(rowptr + rpOff[r], scol + eOff[r],
                                                sval + eOff[r], t,
                                                nxt + (size_t)kOFF[r] * CDIM, kNR[r]);
        }
    }

    head_kernel<<<(kNR[0] + 7) / 8, 256>>>(xb + (size_t)kOFF[0] * CDIM, W_out, b_out, (float*)d_out, kNR[0]);
}